// round 10
// baseline (speedup 1.0000x reference)
#include <cuda_runtime.h>
#include <cuda_bf16.h>
#include <math.h>
#include <stdint.h>

#define Bsz 16
#define NKG 1024
#define SLM 1024
#define Dd  1024
#define Hh  4096

// ---- scratch (device globals: allocation-free) ----
__device__ float g_logits[(size_t)Bsz * NKG * SLM];   // 64 MB
__device__ float g_norm[(size_t)Bsz * NKG * Dd];      // 64 MB (bf16 norm uses half)
__device__ float g_h[(size_t)Bsz * NKG * Hh];         // 256 MB (bf16 h + W1T/W2T in spare)
__device__ float g_lse[Bsz * SLM];
__device__ float g_corr[Bsz * Dd];
__device__ float g_logmask[Bsz * SLM];

__device__ __forceinline__ uint32_t smem_to_u32(const void* p) {
    uint32_t a;
    asm("{ .reg .u64 t; cvta.to.shared.u64 t, %1; cvt.u32.u64 %0, t; }"
        : "=r"(a) : "l"(p));
    return a;
}
__device__ __forceinline__ void cpa16(uint32_t dst, const void* src) {
    asm volatile("cp.async.cg.shared.global [%0], [%1], 16;"
                 :: "r"(dst), "l"(src));
}
#define CP_COMMIT() asm volatile("cp.async.commit_group;" ::: "memory")
#define CP_WAIT(n)  asm volatile("cp.async.wait_group %0;" :: "n"(n) : "memory")

// ======================= tf32 HMMA GEMM (attention) =======================
// C[M,N] = A[M,K] fp32 * op(B); TRANSB: B [N,K], else B [K,N]. Per-batch (z).
// EPI 0: C = acc + vv[col]           EPI 1: C = m2[idx] + acc - vv[col]
// Block 128x256x16, 8 warps (2M x 4N), warp tile 64x64, mma m16n8k8.
// fp32 bits fed to tf32 mma directly (HW truncation). cp.async double buffer.
#define TFPAD 20
#define TFPADB 264
#define TF_AS_U32 (128 * TFPAD)          // 2560 per buffer
#define TF_BS_U32 (256 * TFPAD)          // 5120 per buffer (NN uses 16*264=4224)
#define TF_SMEM_BYTES ((2 * TF_AS_U32 + 2 * TF_BS_U32) * 4)   // 61440

template <bool TRANSB, int EPI>
__global__ __launch_bounds__(256) void tf32_gemm_k(
    const float* __restrict__ A, const float* __restrict__ B, float* __restrict__ C,
    int M, int N, int K,
    size_t sA, size_t sB, size_t sC,
    const float* __restrict__ V1, int sV1,
    const float* __restrict__ M2, size_t sM2)
{
    extern __shared__ uint32_t dsm[];
    uint32_t* Asm = dsm;                       // [2][TF_AS_U32]
    uint32_t* Bsm = dsm + 2 * TF_AS_U32;       // [2][TF_BS_U32]
    const uint32_t s_as = smem_to_u32(Asm);
    const uint32_t s_bs = smem_to_u32(Bsm);

    const int b = blockIdx.z;
    A += (size_t)b * sA;
    B += (size_t)b * sB;
    C += (size_t)b * sC;
    const float* vv = V1 + (size_t)b * sV1;
    const float* m2 = (EPI == 1) ? (M2 + (size_t)b * sM2) : nullptr;

    const int tid  = threadIdx.x;
    const int lane = tid & 31;
    const int wid  = tid >> 5;
    const int wm   = wid & 1;    // 2 M groups of 64
    const int wn   = wid >> 1;   // 4 N groups of 64
    const int bm   = blockIdx.y * 128;
    const int bn   = blockIdx.x * 256;

    float acc[4][8][4];
#pragma unroll
    for (int i = 0; i < 4; i++)
#pragma unroll
        for (int j = 0; j < 8; j++)
#pragma unroll
            for (int c = 0; c < 4; c++) acc[i][j][c] = 0.f;

    auto loadA = [&](int k0, int buf) {
#pragma unroll
        for (int i = 0; i < 2; i++) {
            int id = tid + i * 256;
            int r = id >> 2, c4 = id & 3;
            cpa16(s_as + (buf * TF_AS_U32 + r * TFPAD + c4 * 4) * 4,
                  A + (size_t)(bm + r) * K + k0 + c4 * 4);
        }
    };
    auto loadB = [&](int k0, int buf) {
#pragma unroll
        for (int i = 0; i < 4; i++) {
            int id = tid + i * 256;
            if (TRANSB) {
                int r = id >> 2, c4 = id & 3;
                cpa16(s_bs + (buf * TF_BS_U32 + r * TFPAD + c4 * 4) * 4,
                      B + (size_t)(bn + r) * K + k0 + c4 * 4);
            } else {
                int r = id >> 6, c4 = id & 63;
                cpa16(s_bs + (buf * TF_BS_U32 + r * TFPADB + c4 * 4) * 4,
                      B + (size_t)(k0 + r) * N + bn + c4 * 4);
            }
        }
    };

    loadA(0, 0); loadB(0, 0); CP_COMMIT();

    const int l4 = lane & 3, g = lane >> 2;
    const int nk = K >> 4;
    for (int kt = 0; kt < nk; kt++) {
        const int cur = kt & 1;
        if (kt + 1 < nk) {
            loadA((kt + 1) * 16, cur ^ 1);
            loadB((kt + 1) * 16, cur ^ 1);
            CP_COMMIT();
            CP_WAIT(1);
        } else {
            CP_WAIT(0);
        }
        __syncthreads();

        const uint32_t* Ab = Asm + cur * TF_AS_U32;
        const uint32_t* Bb = Bsm + cur * TF_BS_U32;
#pragma unroll
        for (int ks = 0; ks < 2; ks++) {
            const int kb = ks * 8 + l4;
            uint32_t af[4][4];
#pragma unroll
            for (int mt = 0; mt < 4; mt++) {
                const uint32_t* ab = &Ab[(wm * 64 + mt * 16 + g) * TFPAD + kb];
                af[mt][0] = ab[0];
                af[mt][1] = ab[8 * TFPAD];
                af[mt][2] = ab[4];
                af[mt][3] = ab[8 * TFPAD + 4];
            }
            uint32_t bf[8][2];
#pragma unroll
            for (int nt = 0; nt < 8; nt++) {
                if (TRANSB) {
                    const uint32_t* bb = &Bb[(wn * 64 + nt * 8 + g) * TFPAD + kb];
                    bf[nt][0] = bb[0];
                    bf[nt][1] = bb[4];
                } else {
                    const uint32_t* bb = &Bb[kb * TFPADB + wn * 64 + nt * 8 + g];
                    bf[nt][0] = bb[0];
                    bf[nt][1] = bb[4 * TFPADB];
                }
            }
#pragma unroll
            for (int mt = 0; mt < 4; mt++)
#pragma unroll
                for (int nt = 0; nt < 8; nt++) {
                    asm volatile(
                        "mma.sync.aligned.m16n8k8.row.col.f32.tf32.tf32.f32 "
                        "{%0,%1,%2,%3}, {%4,%5,%6,%7}, {%8,%9}, {%0,%1,%2,%3};"
                        : "+f"(acc[mt][nt][0]), "+f"(acc[mt][nt][1]),
                          "+f"(acc[mt][nt][2]), "+f"(acc[mt][nt][3])
                        : "r"(af[mt][0]), "r"(af[mt][1]),
                          "r"(af[mt][2]), "r"(af[mt][3]),
                          "r"(bf[nt][0]), "r"(bf[nt][1]));
                }
        }
        __syncthreads();
    }

    const int q  = lane >> 2;
    const int cc = (lane & 3) << 1;
#pragma unroll
    for (int mt = 0; mt < 4; mt++) {
        const int r0 = bm + wm * 64 + mt * 16 + q;
#pragma unroll
        for (int nt = 0; nt < 8; nt++) {
            const int col = bn + wn * 64 + nt * 8 + cc;
            const float vx = vv[col], vy = vv[col + 1];
            size_t i0 = (size_t)r0 * N + col;
            size_t i1 = (size_t)(r0 + 8) * N + col;
            float2 o0, o1;
            if (EPI == 0) {
                o0 = make_float2(acc[mt][nt][0] + vx, acc[mt][nt][1] + vy);
                o1 = make_float2(acc[mt][nt][2] + vx, acc[mt][nt][3] + vy);
            } else {
                float2 k0 = *(const float2*)(m2 + i0);
                float2 k1 = *(const float2*)(m2 + i1);
                o0 = make_float2(k0.x + acc[mt][nt][0] - vx, k0.y + acc[mt][nt][1] - vy);
                o1 = make_float2(k1.x + acc[mt][nt][2] - vx, k1.y + acc[mt][nt][3] - vy);
            }
            *(float2*)(C + i0) = o0;
            *(float2*)(C + i1) = o1;
        }
    }
}

// ======================= bf16 HMMA GEMM (FFN) =======================
// Block 128(M)x256(N)xK32, 8 warps (2M x 4N), warp tile 64x64, mma m16n8k16.
// A [M,K] bf16 K-major; B stored [N,K] bf16 K-major. cp.async double buffer.
// SMEM per buffer: A 128x64B (8KB) + B 256x64B (16KB); swizzle pc = kc^((r>>1)&3).
template <int EPI>
__global__ __launch_bounds__(256) void hmma_ffn_k(
    const __nv_bfloat16* __restrict__ A, const __nv_bfloat16* __restrict__ Bw,
    int K, int ldA, int ldB,
    const float* __restrict__ bias,
    float* __restrict__ outF, __nv_bfloat16* __restrict__ outH, int ldOut)
{
    __shared__ __align__(128) char smem[2][24576];   // [buf][A 8KB | B 16KB]
    const int tid  = threadIdx.x;
    const int lane = tid & 31;
    const int wid  = tid >> 5;
    const int wm   = wid & 1;
    const int wn   = wid >> 1;
    const int bm   = blockIdx.y * 128;
    const int bn   = blockIdx.x * 256;
    const uint32_t sbase = smem_to_u32(smem);

    float acc[4][8][4];
#pragma unroll
    for (int i = 0; i < 4; i++)
#pragma unroll
        for (int j = 0; j < 8; j++)
#pragma unroll
            for (int c = 0; c < 4; c++) acc[i][j][c] = 0.f;

    auto loadAB = [&](int k0, int buf) {
        const uint32_t abase = sbase + buf * 24576;
        const uint32_t bbase = abase + 8192;
#pragma unroll
        for (int i = 0; i < 2; i++) {
            int id = tid + i * 256;
            int r = id >> 2, kc = id & 3;
            int pc = kc ^ ((r >> 1) & 3);
            cpa16(abase + r * 64 + pc * 16,
                  A + (size_t)(bm + r) * ldA + k0 + kc * 8);
        }
#pragma unroll
        for (int i = 0; i < 4; i++) {
            int id = tid + i * 256;
            int r = id >> 2, kc = id & 3;
            int pc = kc ^ ((r >> 1) & 3);
            cpa16(bbase + r * 64 + pc * 16,
                  Bw + (size_t)(bn + r) * ldB + k0 + kc * 8);
        }
    };

    loadAB(0, 0); CP_COMMIT();

    const int nk = K >> 5;
    for (int kt = 0; kt < nk; kt++) {
        const int cur = kt & 1;
        if (kt + 1 < nk) {
            loadAB((kt + 1) * 32, cur ^ 1);
            CP_COMMIT();
            CP_WAIT(1);
        } else {
            CP_WAIT(0);
        }
        __syncthreads();

        const uint32_t abase = sbase + cur * 24576;
        const uint32_t bbase = abase + 8192;
#pragma unroll
        for (int ks = 0; ks < 2; ks++) {
            const int sub = lane >> 3;
            const int l7  = lane & 7;
            uint32_t af[4][4];
#pragma unroll
            for (int mt = 0; mt < 4; mt++) {
                int r  = wm * 64 + mt * 16 + l7 + ((sub & 1) << 3);
                int kc = ks * 2 + (sub >> 1);
                uint32_t ad = abase + r * 64 + ((kc ^ ((r >> 1) & 3)) << 4);
                asm volatile(
                    "ldmatrix.sync.aligned.m8n8.x4.shared.b16 {%0,%1,%2,%3}, [%4];"
                    : "=r"(af[mt][0]), "=r"(af[mt][1]),
                      "=r"(af[mt][2]), "=r"(af[mt][3])
                    : "r"(ad));
            }
            uint32_t bq[8][2];
#pragma unroll
            for (int j = 0; j < 4; j++) {
                int n  = wn * 64 + (2 * j + (sub >> 1)) * 8 + l7;
                int kc = ks * 2 + (sub & 1);
                uint32_t bd = bbase + n * 64 + ((kc ^ ((n >> 1) & 3)) << 4);
                uint32_t r0, r1, r2, r3;
                asm volatile(
                    "ldmatrix.sync.aligned.m8n8.x4.shared.b16 {%0,%1,%2,%3}, [%4];"
                    : "=r"(r0), "=r"(r1), "=r"(r2), "=r"(r3)
                    : "r"(bd));
                bq[2 * j][0] = r0;     bq[2 * j][1] = r1;
                bq[2 * j + 1][0] = r2; bq[2 * j + 1][1] = r3;
            }
#pragma unroll
            for (int mt = 0; mt < 4; mt++)
#pragma unroll
                for (int nt = 0; nt < 8; nt++) {
                    asm volatile(
                        "mma.sync.aligned.m16n8k16.row.col.f32.bf16.bf16.f32 "
                        "{%0,%1,%2,%3}, {%4,%5,%6,%7}, {%8,%9}, {%0,%1,%2,%3};"
                        : "+f"(acc[mt][nt][0]), "+f"(acc[mt][nt][1]),
                          "+f"(acc[mt][nt][2]), "+f"(acc[mt][nt][3])
                        : "r"(af[mt][0]), "r"(af[mt][1]),
                          "r"(af[mt][2]), "r"(af[mt][3]),
                          "r"(bq[nt][0]), "r"(bq[nt][1]));
                }
        }
        __syncthreads();
    }

    const int q  = lane >> 2;
    const int cc = (lane & 3) << 1;
#pragma unroll
    for (int mt = 0; mt < 4; mt++) {
        const int r0 = bm + wm * 64 + mt * 16 + q;
#pragma unroll
        for (int nt = 0; nt < 8; nt++) {
            const int col = bn + wn * 64 + nt * 8 + cc;
            const float bx = bias[col];
            const float by = bias[col + 1];
            if (EPI == 0) {
                float x0 = fmaxf(acc[mt][nt][0] + bx, 0.f);
                float x1 = fmaxf(acc[mt][nt][1] + by, 0.f);
                float x2 = fmaxf(acc[mt][nt][2] + bx, 0.f);
                float x3 = fmaxf(acc[mt][nt][3] + by, 0.f);
                *(__nv_bfloat162*)(outH + (size_t)r0 * ldOut + col) =
                    __float22bfloat162_rn(make_float2(x0, x1));
                *(__nv_bfloat162*)(outH + (size_t)(r0 + 8) * ldOut + col) =
                    __float22bfloat162_rn(make_float2(x2, x3));
            } else {
                float2* p0 = (float2*)(outF + (size_t)r0 * ldOut + col);
                float2* p1 = (float2*)(outF + (size_t)(r0 + 8) * ldOut + col);
                float2 o0 = *p0, o1 = *p1;
                o0.x += acc[mt][nt][0] + bx;
                o0.y += acc[mt][nt][1] + by;
                o1.x += acc[mt][nt][2] + bx;
                o1.y += acc[mt][nt][3] + by;
                *p0 = o0;
                *p1 = o1;
            }
        }
    }
}

// transpose fp32 [R,C] -> bf16 [C,R]
__global__ __launch_bounds__(256) void transpose_bf16_k(
    const float* __restrict__ in, __nv_bfloat16* __restrict__ out, int R, int C)
{
    __shared__ float t[32][33];
    int tx = threadIdx.x & 31, ty = threadIdx.x >> 5;
    int c0 = blockIdx.x * 32, r0 = blockIdx.y * 32;
#pragma unroll
    for (int i = 0; i < 4; i++)
        t[ty + 8 * i][tx] = in[(size_t)(r0 + ty + 8 * i) * C + c0 + tx];
    __syncthreads();
#pragma unroll
    for (int i = 0; i < 4; i++)
        out[(size_t)(c0 + ty + 8 * i) * R + r0 + tx] = __float2bfloat16(t[tx][ty + 8 * i]);
}

// ======================= small kernels =======================
__global__ __launch_bounds__(256) void logmask_k(const float* __restrict__ mask)
{
    int i = blockIdx.x * 256 + threadIdx.x;
    g_logmask[i] = logf(mask[i] + 1e-45f);
    g_corr[i] = 0.f;
}

__global__ __launch_bounds__(256) void lse_k()
{
    int b = blockIdx.y;
    int s = blockIdx.x * 256 + threadIdx.x;
    const float* col = g_logits + (size_t)b * NKG * SLM + s;
    float m = -INFINITY, sum = 0.f;
    for (int n = 0; n < NKG; n += 8) {
        float x[8];
#pragma unroll
        for (int u = 0; u < 8; u++) x[u] = col[(size_t)(n + u) * SLM];
        float mn = x[0];
#pragma unroll
        for (int u = 1; u < 8; u++) mn = fmaxf(mn, x[u]);
        float mnew = fmaxf(m, mn);
        float p = sum * expf(m - mnew);
#pragma unroll
        for (int u = 0; u < 8; u++) p += expf(x[u] - mnew);
        sum = p;
        m = mnew;
    }
    g_lse[b * SLM + s] = m + logf(sum);
}

__global__ __launch_bounds__(256) void corr_k(const float* __restrict__ lm)
{
    __shared__ float sl[256];
    int b = blockIdx.y;
    int sc = blockIdx.z;
    int tid = threadIdx.x;
    sl[tid] = g_lse[b * SLM + sc * 256 + tid];
    __syncthreads();
    int d = blockIdx.x * 256 + tid;
    const float* L = lm + (size_t)b * SLM * Dd + (size_t)sc * 256 * Dd + d;
    float acc = 0.f;
#pragma unroll 4
    for (int s = 0; s < 256; s++) acc += sl[s] * L[(size_t)s * Dd];
    atomicAdd(&g_corr[b * Dd + d], acc);
}

__global__ __launch_bounds__(256) void ln_k(const float* __restrict__ X,
                                            const float* __restrict__ gamma,
                                            const float* __restrict__ beta,
                                            __nv_bfloat16* __restrict__ Y)
{
    __shared__ float red[256];
    size_t row = blockIdx.x;
    const float* x = X + row * Dd;
    int tid = threadIdx.x;
    float v[4];
#pragma unroll
    for (int i = 0; i < 4; i++) v[i] = x[i * 256 + tid];
    red[tid] = v[0] + v[1] + v[2] + v[3];
    __syncthreads();
    for (int off = 128; off; off >>= 1) {
        if (tid < off) red[tid] += red[tid + off];
        __syncthreads();
    }
    float mu = red[0] * (1.0f / Dd);
    __syncthreads();
    float sq = 0.f;
#pragma unroll
    for (int i = 0; i < 4; i++) {
        float d = v[i] - mu;
        sq += d * d;
    }
    red[tid] = sq;
    __syncthreads();
    for (int off = 128; off; off >>= 1) {
        if (tid < off) red[tid] += red[tid + off];
        __syncthreads();
    }
    float rstd = rsqrtf(red[0] * (1.0f / Dd) + 1e-6f);
    __nv_bfloat16* y = Y + row * Dd;
#pragma unroll
    for (int i = 0; i < 4; i++) {
        int c = i * 256 + tid;
        y[c] = __float2bfloat16((v[i] - mu) * rstd * gamma[c] + beta[c]);
    }
}

// ======================= launch =======================
extern "C" void kernel_launch(void* const* d_in, const int* in_sizes, int n_in,
                              void* d_out, int out_size)
{
    const float* kg    = (const float*)d_in[0];
    const float* lm    = (const float*)d_in[1];
    const float* mask  = (const float*)d_in[2];
    const float* W1    = (const float*)d_in[3];
    const float* b1    = (const float*)d_in[4];
    const float* W2    = (const float*)d_in[5];
    const float* b2    = (const float*)d_in[6];
    const float* gamma = (const float*)d_in[7];
    const float* beta  = (const float*)d_in[8];
    float* out = (float*)d_out;

    static float *logits = nullptr, *nrm = nullptr, *hbuf = nullptr,
                 *corr = nullptr, *lmask = nullptr;
    if (!logits) {
        void* p;
        cudaGetSymbolAddress(&p, g_logits);  logits = (float*)p;
        cudaGetSymbolAddress(&p, g_norm);    nrm    = (float*)p;
        cudaGetSymbolAddress(&p, g_h);       hbuf   = (float*)p;
        cudaGetSymbolAddress(&p, g_corr);    corr   = (float*)p;
        cudaGetSymbolAddress(&p, g_logmask); lmask  = (float*)p;
        cudaFuncSetAttribute(tf32_gemm_k<true, 0>,
                             cudaFuncAttributeMaxDynamicSharedMemorySize, TF_SMEM_BYTES);
        cudaFuncSetAttribute(tf32_gemm_k<false, 1>,
                             cudaFuncAttributeMaxDynamicSharedMemorySize, TF_SMEM_BYTES);
    }

    __nv_bfloat16* normb = (__nv_bfloat16*)nrm;                       // [16384,1024]
    __nv_bfloat16* hb    = (__nv_bfloat16*)hbuf;                      // [16384,4096]
    __nv_bfloat16* W1T   = ((__nv_bfloat16*)hbuf) + (size_t)64 * 1024 * 1024;  // [4096,1024]
    __nv_bfloat16* W2T   = W1T + (size_t)4 * 1024 * 1024;                      // [1024,4096]

    const int Mtot = Bsz * NKG;  // 16384

    // 0) logmask + corr zero
    logmask_k<<<(Bsz * SLM) / 256, 256>>>(mask);

    // weight transposes (bf16, K-major for HMMA B operand)
    transpose_bf16_k<<<dim3(Hh / 32, Dd / 32), 256>>>(W1, W1T, Dd, Hh);
    transpose_bf16_k<<<dim3(Dd / 32, Hh / 32), 256>>>(W2, W2T, Hh, Dd);

    // 1) logits = kg @ lm^T + logmask       (per-batch NT, tf32 HMMA)
    tf32_gemm_k<true, 0><<<dim3(SLM / 256, NKG / 128, Bsz), 256, TF_SMEM_BYTES>>>(
        kg, lm, logits, NKG, SLM, Dd,
        (size_t)NKG * Dd, (size_t)SLM * Dd, (size_t)NKG * SLM,
        lmask, SLM, nullptr, 0);

    // 2) column logsumexp + correction vector
    lse_k<<<dim3(SLM / 256, Bsz), 256>>>();
    corr_k<<<dim3(Dd / 256, Bsz, 4), 256>>>(lm);

    // 3) out1 = kg + logits @ lm - corr  -> d_out   (per-batch NN, tf32 HMMA)
    tf32_gemm_k<false, 1><<<dim3(Dd / 256, NKG / 128, Bsz), 256, TF_SMEM_BYTES>>>(
        logits, lm, out, NKG, Dd, SLM,
        (size_t)NKG * SLM, (size_t)SLM * Dd, (size_t)NKG * Dd,
        corr, Dd, kg, (size_t)NKG * Dd);

    // 4) LayerNorm(out1) -> bf16 norm
    ln_k<<<Mtot, 256>>>(out, gamma, beta, normb);

    // 5) h = relu(norm @ W1 + b1) -> bf16    (HMMA)
    hmma_ffn_k<0><<<dim3(Hh / 256, Mtot / 128), 256>>>(
        normb, W1T, Dd, Dd, Dd, b1, nullptr, hb, Hh);

    // 6) out += h @ W2 + b2                  (HMMA, residual already in d_out)
    hmma_ffn_k<1><<<dim3(Dd / 256, Mtot / 128), 256>>>(
        hb, W2T, Hh, Hh, Hh, b2, out, nullptr, Dd);

    (void)in_sizes; (void)n_in; (void)out_size;
}

// round 12
// speedup vs baseline: 1.7184x; 1.7184x over previous
#include <cuda_runtime.h>
#include <cuda_bf16.h>
#include <math.h>
#include <stdint.h>

#define Bsz 16
#define NKG 1024
#define SLM 1024
#define Dd  1024
#define Hh  4096

// ---- scratch (device globals: allocation-free) ----
__device__ float g_logits[(size_t)Bsz * NKG * SLM];   // 64 MB (tf32-rounded in epilogue)
__device__ float g_norm[(size_t)Bsz * NKG * Dd];      // 64 MB (bf16 norm uses half)
__device__ float g_h[(size_t)Bsz * NKG * Hh];         // 256 MB (bf16 h + W1T/W2T in spare)
__device__ float g_kgr[(size_t)Bsz * NKG * Dd];       // 64 MB tf32-rounded kg
__device__ float g_lmr[(size_t)Bsz * SLM * Dd];       // 64 MB tf32-rounded lm
__device__ float g_lse[Bsz * SLM];
__device__ float g_corr[Bsz * Dd];
__device__ float g_logmask[Bsz * SLM];

__device__ __forceinline__ uint32_t smem_to_u32(const void* p) {
    uint32_t a;
    asm("{ .reg .u64 t; cvta.to.shared.u64 t, %1; cvt.u32.u64 %0, t; }"
        : "=r"(a) : "l"(p));
    return a;
}
__device__ __forceinline__ uint32_t f2tf32(float x) {
    uint32_t r;
    asm("cvt.rna.tf32.f32 %0, %1;" : "=r"(r) : "f"(x));
    return r;
}
__device__ __forceinline__ void cpa16(uint32_t dst, const void* src) {
    asm volatile("cp.async.cg.shared.global [%0], [%1], 16;"
                 :: "r"(dst), "l"(src));
}
#define CP_COMMIT() asm volatile("cp.async.commit_group;" ::: "memory")
#define CP_WAIT(n)  asm volatile("cp.async.wait_group %0;" :: "n"(n) : "memory")

// round fp32 -> tf32-precision fp32 (elementwise prepass)
__global__ __launch_bounds__(256) void round_k(const float* __restrict__ in,
                                               float* __restrict__ out)
{
    size_t i = ((size_t)blockIdx.x * 256 + threadIdx.x) * 4;
    float4 v = *(const float4*)(in + i);
    uint4 o;
    o.x = f2tf32(v.x); o.y = f2tf32(v.y);
    o.z = f2tf32(v.z); o.w = f2tf32(v.w);
    *(uint4*)(out + i) = o;
}

// ======================= tf32 HMMA GEMM (attention) =======================
// C[M,N] = A[M,K] * op(B); inputs pre-rounded to tf32 precision in gmem.
// TRANSB: B [N,K], else B [K,N]. Per-batch (z).
// EPI 0: C = tf32round(acc + vv[col])   EPI 1: C = m2[idx] + acc - vv[col]
// Block 128x128x16, 8 warps (2M x 4N), warp tile 64x32, mma m16n8k8.
#define TFPAD 20
#define TFPADB 136
#define TF_AS_U32 (128 * TFPAD)   // 2560
#define TF_SMEM_BYTES (4 * TF_AS_U32 * 4)   // A[2]+B[2] -> 40960

template <bool TRANSB, int EPI>
__global__ __launch_bounds__(256) void tf32_gemm_k(
    const float* __restrict__ A, const float* __restrict__ B, float* __restrict__ C,
    int M, int N, int K,
    size_t sA, size_t sB, size_t sC,
    const float* __restrict__ V1, int sV1,
    const float* __restrict__ M2, size_t sM2)
{
    extern __shared__ uint32_t dsm[];
    uint32_t* Asm = dsm;                    // [2][TF_AS_U32]
    uint32_t* Bsm = dsm + 2 * TF_AS_U32;    // [2][TF_AS_U32]
    const uint32_t s_as = smem_to_u32(Asm);
    const uint32_t s_bs = smem_to_u32(Bsm);

    const int b = blockIdx.z;
    A += (size_t)b * sA;
    B += (size_t)b * sB;
    C += (size_t)b * sC;
    const float* vv = V1 + (size_t)b * sV1;
    const float* m2 = (EPI == 1) ? (M2 + (size_t)b * sM2) : nullptr;

    const int tid  = threadIdx.x;
    const int lane = tid & 31;
    const int wid  = tid >> 5;
    const int wm   = wid & 1;
    const int wn   = wid >> 1;
    const int bm   = blockIdx.y * 128;
    const int bn   = blockIdx.x * 128;

    float acc[4][4][4];
#pragma unroll
    for (int i = 0; i < 4; i++)
#pragma unroll
        for (int j = 0; j < 4; j++)
#pragma unroll
            for (int c = 0; c < 4; c++) acc[i][j][c] = 0.f;

    auto loadA = [&](int k0, int buf) {
#pragma unroll
        for (int i = 0; i < 2; i++) {
            int id = tid + i * 256;
            int r = id >> 2, c4 = id & 3;
            cpa16(s_as + (buf * TF_AS_U32 + r * TFPAD + c4 * 4) * 4,
                  A + (size_t)(bm + r) * K + k0 + c4 * 4);
        }
    };
    auto loadB = [&](int k0, int buf) {
#pragma unroll
        for (int i = 0; i < 2; i++) {
            int id = tid + i * 256;
            if (TRANSB) {
                int r = id >> 2, c4 = id & 3;
                cpa16(s_bs + (buf * TF_AS_U32 + r * TFPAD + c4 * 4) * 4,
                      B + (size_t)(bn + r) * K + k0 + c4 * 4);
            } else {
                int r = id >> 5, c = id & 31;
                cpa16(s_bs + (buf * TF_AS_U32 + r * TFPADB + c * 4) * 4,
                      B + (size_t)(k0 + r) * N + bn + c * 4);
            }
        }
    };

    loadA(0, 0); loadB(0, 0); CP_COMMIT();

    const int l4 = lane & 3, g = lane >> 2;
    const int nk = K >> 4;
    for (int kt = 0; kt < nk; kt++) {
        const int cur = kt & 1;
        if (kt + 1 < nk) {
            loadA((kt + 1) * 16, cur ^ 1);
            loadB((kt + 1) * 16, cur ^ 1);
            CP_COMMIT();
            CP_WAIT(1);
        } else {
            CP_WAIT(0);
        }
        __syncthreads();

        const uint32_t* Ab = Asm + cur * TF_AS_U32;
        const uint32_t* Bb = Bsm + cur * TF_AS_U32;
#pragma unroll
        for (int ks = 0; ks < 2; ks++) {
            const int kb = ks * 8 + l4;
            uint32_t af[4][4];
#pragma unroll
            for (int mt = 0; mt < 4; mt++) {
                const uint32_t* ab = &Ab[(wm * 64 + mt * 16 + g) * TFPAD + kb];
                af[mt][0] = ab[0];
                af[mt][1] = ab[8 * TFPAD];
                af[mt][2] = ab[4];
                af[mt][3] = ab[8 * TFPAD + 4];
            }
            uint32_t bf[4][2];
#pragma unroll
            for (int nt = 0; nt < 4; nt++) {
                if (TRANSB) {
                    const uint32_t* bb = &Bb[(wn * 32 + nt * 8 + g) * TFPAD + kb];
                    bf[nt][0] = bb[0];
                    bf[nt][1] = bb[4];
                } else {
                    const uint32_t* bb = &Bb[kb * TFPADB + wn * 32 + nt * 8 + g];
                    bf[nt][0] = bb[0];
                    bf[nt][1] = bb[4 * TFPADB];
                }
            }
#pragma unroll
            for (int mt = 0; mt < 4; mt++)
#pragma unroll
                for (int nt = 0; nt < 4; nt++) {
                    asm volatile(
                        "mma.sync.aligned.m16n8k8.row.col.f32.tf32.tf32.f32 "
                        "{%0,%1,%2,%3}, {%4,%5,%6,%7}, {%8,%9}, {%0,%1,%2,%3};"
                        : "+f"(acc[mt][nt][0]), "+f"(acc[mt][nt][1]),
                          "+f"(acc[mt][nt][2]), "+f"(acc[mt][nt][3])
                        : "r"(af[mt][0]), "r"(af[mt][1]),
                          "r"(af[mt][2]), "r"(af[mt][3]),
                          "r"(bf[nt][0]), "r"(bf[nt][1]));
                }
        }
        __syncthreads();
    }

    const int q  = lane >> 2;
    const int cc = (lane & 3) << 1;
#pragma unroll
    for (int mt = 0; mt < 4; mt++) {
        const int r0 = bm + wm * 64 + mt * 16 + q;
#pragma unroll
        for (int nt = 0; nt < 4; nt++) {
            const int col = bn + wn * 32 + nt * 8 + cc;
            const float vx = vv[col], vy = vv[col + 1];
            size_t i0 = (size_t)r0 * N + col;
            size_t i1 = (size_t)(r0 + 8) * N + col;
            float2 o0, o1;
            if (EPI == 0) {
                // round logits to tf32 precision -> GEMM3's A operand is pre-rounded
                o0 = make_float2(__uint_as_float(f2tf32(acc[mt][nt][0] + vx)),
                                 __uint_as_float(f2tf32(acc[mt][nt][1] + vy)));
                o1 = make_float2(__uint_as_float(f2tf32(acc[mt][nt][2] + vx)),
                                 __uint_as_float(f2tf32(acc[mt][nt][3] + vy)));
            } else {
                float2 k0 = *(const float2*)(m2 + i0);
                float2 k1 = *(const float2*)(m2 + i1);
                o0 = make_float2(k0.x + acc[mt][nt][0] - vx, k0.y + acc[mt][nt][1] - vy);
                o1 = make_float2(k1.x + acc[mt][nt][2] - vx, k1.y + acc[mt][nt][3] - vy);
            }
            *(float2*)(C + i0) = o0;
            *(float2*)(C + i1) = o1;
        }
    }
}

// ======================= bf16 HMMA GEMM (FFN) =======================
// Block 128x128x32, 8 warps (2M x 4N), warp tile 64x32, mma m16n8k16.
// A [M,K] bf16 K-major; B [N,K] bf16 K-major. cp.async double buffer.
// SMEM per buffer: A 128x64B (8KB) + B 128x64B (8KB); swizzle pc = kc^((r>>1)&3).
template <int EPI>
__global__ __launch_bounds__(256) void hmma_ffn_k(
    const __nv_bfloat16* __restrict__ A, const __nv_bfloat16* __restrict__ Bw,
    int K, int ldA, int ldB,
    const float* __restrict__ bias,
    float* __restrict__ outF, __nv_bfloat16* __restrict__ outH, int ldOut)
{
    __shared__ __align__(128) char smem[2][16384];   // [buf][A 8KB | B 8KB]
    const int tid  = threadIdx.x;
    const int lane = tid & 31;
    const int wid  = tid >> 5;
    const int wm   = wid & 1;
    const int wn   = wid >> 1;
    const int bm   = blockIdx.y * 128;
    const int bn   = blockIdx.x * 128;
    const uint32_t sbase = smem_to_u32(smem);

    float acc[4][4][4];
#pragma unroll
    for (int i = 0; i < 4; i++)
#pragma unroll
        for (int j = 0; j < 4; j++)
#pragma unroll
            for (int c = 0; c < 4; c++) acc[i][j][c] = 0.f;

    auto loadAB = [&](int k0, int buf) {
        const uint32_t abase = sbase + buf * 16384;
        const uint32_t bbase = abase + 8192;
#pragma unroll
        for (int i = 0; i < 2; i++) {
            int id = tid + i * 256;
            int r = id >> 2, kc = id & 3;
            int pc = kc ^ ((r >> 1) & 3);
            cpa16(abase + r * 64 + pc * 16,
                  A + (size_t)(bm + r) * ldA + k0 + kc * 8);
        }
#pragma unroll
        for (int i = 0; i < 2; i++) {
            int id = tid + i * 256;
            int r = id >> 2, kc = id & 3;
            int pc = kc ^ ((r >> 1) & 3);
            cpa16(bbase + r * 64 + pc * 16,
                  Bw + (size_t)(bn + r) * ldB + k0 + kc * 8);
        }
    };

    loadAB(0, 0); CP_COMMIT();

    const int nk = K >> 5;
    for (int kt = 0; kt < nk; kt++) {
        const int cur = kt & 1;
        if (kt + 1 < nk) {
            loadAB((kt + 1) * 32, cur ^ 1);
            CP_COMMIT();
            CP_WAIT(1);
        } else {
            CP_WAIT(0);
        }
        __syncthreads();

        const uint32_t abase = sbase + cur * 16384;
        const uint32_t bbase = abase + 8192;
#pragma unroll
        for (int ks = 0; ks < 2; ks++) {
            const int sub = lane >> 3;
            const int l7  = lane & 7;
            uint32_t af[4][4];
#pragma unroll
            for (int mt = 0; mt < 4; mt++) {
                int r  = wm * 64 + mt * 16 + l7 + ((sub & 1) << 3);
                int kc = ks * 2 + (sub >> 1);
                uint32_t ad = abase + r * 64 + ((kc ^ ((r >> 1) & 3)) << 4);
                asm volatile(
                    "ldmatrix.sync.aligned.m8n8.x4.shared.b16 {%0,%1,%2,%3}, [%4];"
                    : "=r"(af[mt][0]), "=r"(af[mt][1]),
                      "=r"(af[mt][2]), "=r"(af[mt][3])
                    : "r"(ad));
            }
            uint32_t bq[4][2];
#pragma unroll
            for (int j = 0; j < 2; j++) {
                int n  = wn * 32 + (2 * j + (sub >> 1)) * 8 + l7;
                int kc = ks * 2 + (sub & 1);
                uint32_t bd = bbase + n * 64 + ((kc ^ ((n >> 1) & 3)) << 4);
                uint32_t r0, r1, r2, r3;
                asm volatile(
                    "ldmatrix.sync.aligned.m8n8.x4.shared.b16 {%0,%1,%2,%3}, [%4];"
                    : "=r"(r0), "=r"(r1), "=r"(r2), "=r"(r3)
                    : "r"(bd));
                bq[2 * j][0] = r0;     bq[2 * j][1] = r1;
                bq[2 * j + 1][0] = r2; bq[2 * j + 1][1] = r3;
            }
#pragma unroll
            for (int mt = 0; mt < 4; mt++)
#pragma unroll
                for (int nt = 0; nt < 4; nt++) {
                    asm volatile(
                        "mma.sync.aligned.m16n8k16.row.col.f32.bf16.bf16.f32 "
                        "{%0,%1,%2,%3}, {%4,%5,%6,%7}, {%8,%9}, {%0,%1,%2,%3};"
                        : "+f"(acc[mt][nt][0]), "+f"(acc[mt][nt][1]),
                          "+f"(acc[mt][nt][2]), "+f"(acc[mt][nt][3])
                        : "r"(af[mt][0]), "r"(af[mt][1]),
                          "r"(af[mt][2]), "r"(af[mt][3]),
                          "r"(bq[nt][0]), "r"(bq[nt][1]));
                }
        }
        __syncthreads();
    }

    const int q  = lane >> 2;
    const int cc = (lane & 3) << 1;
#pragma unroll
    for (int mt = 0; mt < 4; mt++) {
        const int r0 = bm + wm * 64 + mt * 16 + q;
#pragma unroll
        for (int nt = 0; nt < 4; nt++) {
            const int col = bn + wn * 32 + nt * 8 + cc;
            const float bx = bias[col];
            const float by = bias[col + 1];
            if (EPI == 0) {
                float x0 = fmaxf(acc[mt][nt][0] + bx, 0.f);
                float x1 = fmaxf(acc[mt][nt][1] + by, 0.f);
                float x2 = fmaxf(acc[mt][nt][2] + bx, 0.f);
                float x3 = fmaxf(acc[mt][nt][3] + by, 0.f);
                *(__nv_bfloat162*)(outH + (size_t)r0 * ldOut + col) =
                    __float22bfloat162_rn(make_float2(x0, x1));
                *(__nv_bfloat162*)(outH + (size_t)(r0 + 8) * ldOut + col) =
                    __float22bfloat162_rn(make_float2(x2, x3));
            } else {
                float2* p0 = (float2*)(outF + (size_t)r0 * ldOut + col);
                float2* p1 = (float2*)(outF + (size_t)(r0 + 8) * ldOut + col);
                float2 o0 = *p0, o1 = *p1;
                o0.x += acc[mt][nt][0] + bx;
                o0.y += acc[mt][nt][1] + by;
                o1.x += acc[mt][nt][2] + bx;
                o1.y += acc[mt][nt][3] + by;
                *p0 = o0;
                *p1 = o1;
            }
        }
    }
}

// transpose fp32 [R,C] -> bf16 [C,R]
__global__ __launch_bounds__(256) void transpose_bf16_k(
    const float* __restrict__ in, __nv_bfloat16* __restrict__ out, int R, int C)
{
    __shared__ float t[32][33];
    int tx = threadIdx.x & 31, ty = threadIdx.x >> 5;
    int c0 = blockIdx.x * 32, r0 = blockIdx.y * 32;
#pragma unroll
    for (int i = 0; i < 4; i++)
        t[ty + 8 * i][tx] = in[(size_t)(r0 + ty + 8 * i) * C + c0 + tx];
    __syncthreads();
#pragma unroll
    for (int i = 0; i < 4; i++)
        out[(size_t)(c0 + ty + 8 * i) * R + r0 + tx] = __float2bfloat16(t[tx][ty + 8 * i]);
}

// ======================= small kernels =======================
__global__ __launch_bounds__(256) void logmask_k(const float* __restrict__ mask)
{
    int i = blockIdx.x * 256 + threadIdx.x;
    g_logmask[i] = logf(mask[i] + 1e-45f);
    g_corr[i] = 0.f;
}

__global__ __launch_bounds__(256) void lse_k()
{
    int b = blockIdx.y;
    int s = blockIdx.x * 256 + threadIdx.x;
    const float* col = g_logits + (size_t)b * NKG * SLM + s;
    float m = -INFINITY, sum = 0.f;
    for (int n = 0; n < NKG; n += 8) {
        float x[8];
#pragma unroll
        for (int u = 0; u < 8; u++) x[u] = col[(size_t)(n + u) * SLM];
        float mn = x[0];
#pragma unroll
        for (int u = 1; u < 8; u++) mn = fmaxf(mn, x[u]);
        float mnew = fmaxf(m, mn);
        float p = sum * expf(m - mnew);
#pragma unroll
        for (int u = 0; u < 8; u++) p += expf(x[u] - mnew);
        sum = p;
        m = mnew;
    }
    g_lse[b * SLM + s] = m + logf(sum);
}

__global__ __launch_bounds__(256) void corr_k(const float* __restrict__ lm)
{
    __shared__ float sl[256];
    int b = blockIdx.y;
    int sc = blockIdx.z;
    int tid = threadIdx.x;
    sl[tid] = g_lse[b * SLM + sc * 256 + tid];
    __syncthreads();
    int d = blockIdx.x * 256 + tid;
    const float* L = lm + (size_t)b * SLM * Dd + (size_t)sc * 256 * Dd + d;
    float acc = 0.f;
#pragma unroll 4
    for (int s = 0; s < 256; s++) acc += sl[s] * L[(size_t)s * Dd];
    atomicAdd(&g_corr[b * Dd + d], acc);
}

__global__ __launch_bounds__(256) void ln_k(const float* __restrict__ X,
                                            const float* __restrict__ gamma,
                                            const float* __restrict__ beta,
                                            __nv_bfloat16* __restrict__ Y)
{
    __shared__ float red[256];
    size_t row = blockIdx.x;
    const float* x = X + row * Dd;
    int tid = threadIdx.x;
    float v[4];
#pragma unroll
    for (int i = 0; i < 4; i++) v[i] = x[i * 256 + tid];
    red[tid] = v[0] + v[1] + v[2] + v[3];
    __syncthreads();
    for (int off = 128; off; off >>= 1) {
        if (tid < off) red[tid] += red[tid + off];
        __syncthreads();
    }
    float mu = red[0] * (1.0f / Dd);
    __syncthreads();
    float sq = 0.f;
#pragma unroll
    for (int i = 0; i < 4; i++) {
        float d = v[i] - mu;
        sq += d * d;
    }
    red[tid] = sq;
    __syncthreads();
    for (int off = 128; off; off >>= 1) {
        if (tid < off) red[tid] += red[tid + off];
        __syncthreads();
    }
    float rstd = rsqrtf(red[0] * (1.0f / Dd) + 1e-6f);
    __nv_bfloat16* y = Y + row * Dd;
#pragma unroll
    for (int i = 0; i < 4; i++) {
        int c = i * 256 + tid;
        y[c] = __float2bfloat16((v[i] - mu) * rstd * gamma[c] + beta[c]);
    }
}

// ======================= launch =======================
extern "C" void kernel_launch(void* const* d_in, const int* in_sizes, int n_in,
                              void* d_out, int out_size)
{
    const float* kg    = (const float*)d_in[0];
    const float* lm    = (const float*)d_in[1];
    const float* mask  = (const float*)d_in[2];
    const float* W1    = (const float*)d_in[3];
    const float* b1    = (const float*)d_in[4];
    const float* W2    = (const float*)d_in[5];
    const float* b2    = (const float*)d_in[6];
    const float* gamma = (const float*)d_in[7];
    const float* beta  = (const float*)d_in[8];
    float* out = (float*)d_out;

    static float *logits = nullptr, *nrm = nullptr, *hbuf = nullptr,
                 *corr = nullptr, *lmask = nullptr, *kgr = nullptr, *lmr = nullptr;
    if (!logits) {
        void* p;
        cudaGetSymbolAddress(&p, g_logits);  logits = (float*)p;
        cudaGetSymbolAddress(&p, g_norm);    nrm    = (float*)p;
        cudaGetSymbolAddress(&p, g_h);       hbuf   = (float*)p;
        cudaGetSymbolAddress(&p, g_kgr);     kgr    = (float*)p;
        cudaGetSymbolAddress(&p, g_lmr);     lmr    = (float*)p;
        cudaGetSymbolAddress(&p, g_corr);    corr   = (float*)p;
        cudaGetSymbolAddress(&p, g_logmask); lmask  = (float*)p;
        cudaFuncSetAttribute(tf32_gemm_k<true, 0>,
                             cudaFuncAttributeMaxDynamicSharedMemorySize, TF_SMEM_BYTES);
        cudaFuncSetAttribute(tf32_gemm_k<false, 1>,
                             cudaFuncAttributeMaxDynamicSharedMemorySize, TF_SMEM_BYTES);
    }

    __nv_bfloat16* normb = (__nv_bfloat16*)nrm;                       // [16384,1024]
    __nv_bfloat16* hb    = (__nv_bfloat16*)hbuf;                      // [16384,4096]
    __nv_bfloat16* W1T   = ((__nv_bfloat16*)hbuf) + (size_t)64 * 1024 * 1024;  // [4096,1024]
    __nv_bfloat16* W2T   = W1T + (size_t)4 * 1024 * 1024;                      // [1024,4096]

    const int Mtot = Bsz * NKG;  // 16384
    const size_t NEl = (size_t)Bsz * NKG * Dd;  // 16Mi

    // 0) logmask + corr zero; tf32-round kg and lm into scratch
    logmask_k<<<(Bsz * SLM) / 256, 256>>>(mask);
    round_k<<<(int)(NEl / 4 / 256), 256>>>(kg, kgr);
    round_k<<<(int)(NEl / 4 / 256), 256>>>(lm, lmr);

    // weight transposes (bf16, K-major for HMMA B operand)
    transpose_bf16_k<<<dim3(Hh / 32, Dd / 32), 256>>>(W1, W1T, Dd, Hh);
    transpose_bf16_k<<<dim3(Dd / 32, Hh / 32), 256>>>(W2, W2T, Hh, Dd);

    // 1) logits = round(kg_r @ lm_r^T + logmask)   (per-batch NT, tf32 HMMA)
    tf32_gemm_k<true, 0><<<dim3(SLM / 128, NKG / 128, Bsz), 256, TF_SMEM_BYTES>>>(
        kgr, lmr, logits, NKG, SLM, Dd,
        (size_t)NKG * Dd, (size_t)SLM * Dd, (size_t)NKG * SLM,
        lmask, SLM, nullptr, 0);

    // 2) column logsumexp + correction vector (uses rounded lm for consistency)
    lse_k<<<dim3(SLM / 256, Bsz), 256>>>();
    corr_k<<<dim3(Dd / 256, Bsz, 4), 256>>>(lmr);

    // 3) out1 = kg + logits @ lm_r - corr  -> d_out   (per-batch NN, tf32 HMMA)
    tf32_gemm_k<false, 1><<<dim3(Dd / 128, NKG / 128, Bsz), 256, TF_SMEM_BYTES>>>(
        logits, lmr, out, NKG, Dd, SLM,
        (size_t)NKG * SLM, (size_t)SLM * Dd, (size_t)NKG * Dd,
        corr, Dd, kg, (size_t)NKG * Dd);

    // 4) LayerNorm(out1) -> bf16 norm
    ln_k<<<Mtot, 256>>>(out, gamma, beta, normb);

    // 5) h = relu(norm @ W1 + b1) -> bf16    (HMMA + cp.async)
    hmma_ffn_k<0><<<dim3(Hh / 128, Mtot / 128), 256>>>(
        normb, W1T, Dd, Dd, Dd, b1, nullptr, hb, Hh);

    // 6) out += h @ W2 + b2                  (HMMA + cp.async, residual in d_out)
    hmma_ffn_k<1><<<dim3(Dd / 128, Mtot / 128), 256>>>(
        hb, W2T, Hh, Hh, Hh, b2, out, nullptr, Dd);

    (void)in_sizes; (void)n_in; (void)out_size;
}